// round 6
// baseline (speedup 1.0000x reference)
#include <cuda_runtime.h>
#include <cstdint>

#define CC   64
#define IC   16
#define NPIX 4096   // 64x64
#define BB   4

// ---------------- scratch (device globals; no allocation allowed) ----------------
__device__ float d_th [BB * NPIX * IC];          // queries
__device__ float d_ph [BB * NPIX * IC];          // keys
__device__ float d_gx [BB * NPIX * IC];          // values
__device__ float d_pacc[2 * BB * NPIX * IC];     // split-K partial numerators
__device__ float d_pl  [2 * BB * NPIX];          // split-K partial denominators
__device__ float d_y  [BB * NPIX * IC];          // attention output
__device__ float d_z  [BB * CC * 128 * 128];     // residual sum pre-BN
__device__ float d_csum[CC];
__device__ float d_csq [CC];

// ---------------- f32x2 packed helpers ----------------
__device__ __forceinline__ unsigned long long f2fma(unsigned long long a, unsigned long long b, unsigned long long c) {
    unsigned long long d;
    asm("fma.rn.f32x2 %0, %1, %2, %3;" : "=l"(d) : "l"(a), "l"(b), "l"(c));
    return d;
}
__device__ __forceinline__ unsigned long long f2mul(unsigned long long a, unsigned long long b) {
    unsigned long long d;
    asm("mul.rn.f32x2 %0, %1, %2;" : "=l"(d) : "l"(a), "l"(b));
    return d;
}
__device__ __forceinline__ unsigned long long f2pack(float lo, float hi) {
    unsigned long long d;
    asm("mov.b64 %0, {%1, %2};" : "=l"(d) : "f"(lo), "f"(hi));
    return d;
}
__device__ __forceinline__ void f2unpack(unsigned long long v, float& lo, float& hi) {
    asm("mov.b64 {%0, %1}, %2;" : "=f"(lo), "=f"(hi) : "l"(v));
}

// ================= Kernel A: odd-pixel decimation + 3 fused 1x1 projections =================
// sample_f = 2o+1 exactly on-pixel => xd[oh,ow] = x[2oh+1, 2ow+1]
__global__ void proj_kernel(const float* __restrict__ x,
                            const float* __restrict__ gw, const float* __restrict__ gb,
                            const float* __restrict__ tw, const float* __restrict__ tb,
                            const float* __restrict__ pw, const float* __restrict__ pb) {
    __shared__ float swg[IC * CC], swt[IC * CC], swp[IC * CC];
    __shared__ float sbg[IC], sbt[IC], sbp[IC];
    int tid = threadIdx.x;
    for (int i = tid; i < IC * CC; i += blockDim.x) { swg[i] = gw[i]; swt[i] = tw[i]; swp[i] = pw[i]; }
    if (tid < IC) { sbg[tid] = gb[tid]; sbt[tid] = tb[tid]; sbp[tid] = pb[tid]; }
    if (blockIdx.x == 0 && tid < CC) { d_csum[tid] = 0.f; d_csq[tid] = 0.f; }  // re-zero stats each replay
    __syncthreads();

    int gidx = blockIdx.x * blockDim.x + tid;     // 0..16383 = b*4096 + p
    int b = gidx >> 12;
    int p = gidx & (NPIX - 1);
    int oh = p >> 6, ow = p & 63;
    // pixel (2*oh+1, 2*ow+1)
    const float* xb = x + ((size_t)(b * CC) * 128 + 2 * oh + 1) * 128 + 2 * ow + 1;

    float ag[IC], at[IC], ap[IC];
#pragma unroll
    for (int o = 0; o < IC; o++) { ag[o] = 0.f; at[o] = 0.f; ap[o] = 0.f; }

    for (int c = 0; c < CC; c++) {
        float xv = xb[(size_t)c * 128 * 128];
#pragma unroll
        for (int o = 0; o < IC; o++) {
            ag[o] += swg[o * CC + c] * xv;
            at[o] += swt[o * CC + c] * xv;
            ap[o] += swp[o * CC + c] * xv;
        }
    }
    float* tho = d_th + (size_t)gidx * IC;
    float* pho = d_ph + (size_t)gidx * IC;
    float* gxo = d_gx + (size_t)gidx * IC;
#pragma unroll
    for (int o = 0; o < IC; o++) {
        tho[o] = at[o] + sbt[o];
        pho[o] = ap[o] + sbp[o];
        gxo[o] = ag[o] + sbg[o];
    }
}

// ================= Kernel B: streaming softmax attention (no running max needed) =======
// scores std ~4, max < ~25 => exp sums stay far inside fp32 range.
// grid: (16 qtiles, 2 ksplits, 4 batches), 256 threads, 1 query per thread.
__global__ void attn_kernel() {
    __shared__ float sk[128 * IC];
    __shared__ float sg[128 * IC];
    int tid = threadIdx.x;
    int b  = blockIdx.z;
    int ks = blockIdx.y;
    int q  = blockIdx.x * 256 + tid;

    const unsigned long long* qp = (const unsigned long long*)(d_th + ((size_t)b * NPIX + q) * IC);
    unsigned long long q2[8];
#pragma unroll
    for (int i = 0; i < 8; i++) q2[i] = qp[i];

    unsigned long long acc2[8];
#pragma unroll
    for (int i = 0; i < 8; i++) acc2[i] = 0ull;
    float l = 0.f;

    int k0 = ks * 2048;
    for (int kt = 0; kt < 2048; kt += 128) {
        const float4* srck = (const float4*)(d_ph + ((size_t)b * NPIX + k0 + kt) * IC);
        const float4* srcg = (const float4*)(d_gx + ((size_t)b * NPIX + k0 + kt) * IC);
        float4* dk = (float4*)sk;
        float4* dg = (float4*)sg;
        dk[tid] = srck[tid]; dk[tid + 256] = srck[tid + 256];
        dg[tid] = srcg[tid]; dg[tid + 256] = srcg[tid + 256];
        __syncthreads();

        const unsigned long long* k2 = (const unsigned long long*)sk;
        const unsigned long long* g2 = (const unsigned long long*)sg;
#pragma unroll 4
        for (int j = 0; j < 128; j++) {
            const unsigned long long* kj = k2 + j * 8;
            const unsigned long long* gj = g2 + j * 8;
            unsigned long long s2 = f2mul(q2[0], kj[0]);
#pragma unroll
            for (int i = 1; i < 8; i++) s2 = f2fma(q2[i], kj[i], s2);
            float slo, shi; f2unpack(s2, slo, shi);
            float pexp = __expf(slo + shi);
            l += pexp;
            unsigned long long p2 = f2pack(pexp, pexp);
#pragma unroll
            for (int i = 0; i < 8; i++) acc2[i] = f2fma(p2, gj[i], acc2[i]);
        }
        __syncthreads();
    }

    float* pa = d_pacc + (((size_t)ks * BB + b) * NPIX + q) * IC;
#pragma unroll
    for (int i = 0; i < 8; i++) {
        float lo, hi; f2unpack(acc2[i], lo, hi);
        pa[2 * i] = lo; pa[2 * i + 1] = hi;
    }
    d_pl[((size_t)ks * BB + b) * NPIX + q] = l;
}

// ================= Kernel B2: combine the 2 key-split partials =================
__global__ void combine_kernel() {
    int idx = blockIdx.x * blockDim.x + threadIdx.x;        // 0 .. BB*NPIX*IC-1
    int bq = idx >> 4;
    float l = d_pl[bq] + d_pl[BB * NPIX + bq];
    d_y[idx] = (d_pacc[idx] + d_pacc[BB * NPIX * IC + idx]) / l;
}

// ================= Kernel C: upsample x2 + out-proj + residual + BN stats =================
// upsample sample coord = 0.5*h - 0.5 (jax edge renormalization == clamp at these taps)
// grid: 512 blocks = (b, h); 256 threads.
__global__ void up_kernel(const float* __restrict__ x,
                          const float* __restrict__ ow_, const float* __restrict__ ob_) {
    __shared__ float sy0[64 * IC], sy1[64 * IC];
    __shared__ float syu[128 * IC];
    __shared__ float sw[CC * IC];
    __shared__ float sob[CC];
    __shared__ float psum[256], psq[256];

    int tid = threadIdx.x;
    int bx = blockIdx.x;
    int b = bx >> 7;
    int h = bx & 127;

    for (int i = tid; i < CC * IC; i += 256) sw[i] = ow_[i];
    if (tid < CC) sob[tid] = ob_[tid];

    // vertical taps: s = 0.5h - 0.5
    float sh = 0.5f * (float)h - 0.5f;
    int j0 = (int)floorf(sh);
    float fh = sh - (float)j0;
    int j1 = min(j0 + 1, 63);
    j0 = max(j0, 0);

    const float* yb = d_y + (size_t)b * NPIX * IC;
    ((float4*)sy0)[tid] = ((const float4*)(yb + (size_t)j0 * 64 * IC))[tid];
    ((float4*)sy1)[tid] = ((const float4*)(yb + (size_t)j1 * 64 * IC))[tid];
    __syncthreads();

    // horizontal interp: 2 threads per output w, 8 channels each
    {
        int w = tid >> 1;
        int ibase = (tid & 1) * 8;
        float swc = 0.5f * (float)w - 0.5f;
        int i0 = (int)floorf(swc);
        float fw = swc - (float)i0;
        int i1 = min(i0 + 1, 63);
        i0 = max(i0, 0);
        float w00 = (1.f - fh) * (1.f - fw), w01 = (1.f - fh) * fw;
        float w10 = fh * (1.f - fw),         w11 = fh * fw;
#pragma unroll
        for (int i = 0; i < 8; i++) {
            int ii = ibase + i;
            syu[w * IC + ii] = w00 * sy0[i0 * IC + ii] + w01 * sy0[i1 * IC + ii]
                             + w10 * sy1[i0 * IC + ii] + w11 * sy1[i1 * IC + ii];
        }
    }
    __syncthreads();

    // out projection + residual + stats: thread (c, pg) covers 32 pixels of the row
    int c = tid >> 2, pg = tid & 3;
    const float* wr = sw + c * IC;
    size_t rowoff = ((size_t)(b * CC + c) * 128 + h) * 128 + pg * 32;
    const float* xrow = x + rowoff;
    float* zrow = d_z + rowoff;
    float bias = sob[c];
    float s1 = 0.f, s2 = 0.f;
#pragma unroll 4
    for (int w = 0; w < 32; w++) {
        const float* yu = syu + (pg * 32 + w) * IC;
        float acc = bias;
#pragma unroll
        for (int i = 0; i < IC; i++) acc += wr[i] * yu[i];
        float z = xrow[w] + acc;
        zrow[w] = z;
        s1 += z; s2 += z * z;
    }
    psum[tid] = s1; psq[tid] = s2;
    __syncthreads();
    if (pg == 0) {
        float a = psum[tid] + psum[tid + 1] + psum[tid + 2] + psum[tid + 3];
        float qq = psq[tid] + psq[tid + 1] + psq[tid + 2] + psq[tid + 3];
        atomicAdd(&d_csum[c], a);
        atomicAdd(&d_csq[c], qq);
    }
}

// ================= Kernel D: batchnorm normalize =================
__global__ void bn_kernel(const float* __restrict__ gamma, const float* __restrict__ beta,
                          float* __restrict__ out) {
    int idx = blockIdx.x * blockDim.x + threadIdx.x;  // float4 index, 0 .. 1048575
    int c = (idx >> 12) & 63;                         // 4096 float4 per (b,c) plane
    const float inv = 1.f / 65536.f;
    float mean = d_csum[c] * inv;
    float var = d_csq[c] * inv - mean * mean;
    float rstd = rsqrtf(var + 1e-5f);
    float g = gamma[c] * rstd;
    float bt = beta[c] - mean * g;
    float4 z = ((const float4*)d_z)[idx];
    float4 o;
    o.x = z.x * g + bt; o.y = z.y * g + bt; o.z = z.z * g + bt; o.w = z.w * g + bt;
    ((float4*)out)[idx] = o;
}

// ================= launch =================
extern "C" void kernel_launch(void* const* d_in, const int* in_sizes, int n_in,
                              void* d_out, int out_size) {
    const float* x     = (const float*)d_in[0];
    const float* g_w   = (const float*)d_in[1];
    const float* g_b   = (const float*)d_in[2];
    const float* th_w  = (const float*)d_in[3];
    const float* th_b  = (const float*)d_in[4];
    const float* ph_w  = (const float*)d_in[5];
    const float* ph_b  = (const float*)d_in[6];
    const float* out_w = (const float*)d_in[7];
    const float* out_b = (const float*)d_in[8];
    const float* bn_g  = (const float*)d_in[9];
    const float* bn_b  = (const float*)d_in[10];
    float* out = (float*)d_out;

    proj_kernel<<<128, 128>>>(x, g_w, g_b, th_w, th_b, ph_w, ph_b);
    attn_kernel<<<dim3(16, 2, 4), 256>>>();
    combine_kernel<<<BB * NPIX * IC / 256, 256>>>();
    up_kernel<<<BB * 128, 256>>>(x, out_w, out_b);
    bn_kernel<<<4096, 256>>>(bn_g, bn_b, out);
}

// round 9
// speedup vs baseline: 1.1689x; 1.1689x over previous
#include <cuda_runtime.h>
#include <cstdint>

#define CC   64
#define IC   16
#define NPIX 4096   // 64x64
#define BB   4
#define KSPLIT 8

// ---------------- scratch (device globals; no allocation allowed) ----------------
__device__ float d_th [BB * NPIX * IC];              // queries (pre-scaled by log2e)
__device__ float d_ph [BB * NPIX * IC];              // keys
__device__ float d_gx [BB * NPIX * IC];              // values
__device__ float d_pacc[KSPLIT * BB * NPIX * IC];    // split-K partial numerators
__device__ float d_pl  [KSPLIT * BB * NPIX];         // split-K partial denominators
__device__ float d_yp [BB * CC * NPIX];              // attention out, PROJECTED to 64ch, [b][c][n]
__device__ float d_z  [BB * CC * 128 * 128];         // residual sum pre-BN
__device__ float d_csum[CC];
__device__ float d_csq [CC];

// ---------------- f32x2 packed helpers ----------------
__device__ __forceinline__ unsigned long long f2fma(unsigned long long a, unsigned long long b, unsigned long long c) {
    unsigned long long d;
    asm("fma.rn.f32x2 %0, %1, %2, %3;" : "=l"(d) : "l"(a), "l"(b), "l"(c));
    return d;
}
__device__ __forceinline__ unsigned long long f2mul(unsigned long long a, unsigned long long b) {
    unsigned long long d;
    asm("mul.rn.f32x2 %0, %1, %2;" : "=l"(d) : "l"(a), "l"(b));
    return d;
}
__device__ __forceinline__ unsigned long long f2pack(float lo, float hi) {
    unsigned long long d;
    asm("mov.b64 %0, {%1, %2};" : "=l"(d) : "f"(lo), "f"(hi));
    return d;
}
__device__ __forceinline__ void f2unpack(unsigned long long v, float& lo, float& hi) {
    asm("mov.b64 {%0, %1}, %2;" : "=f"(lo), "=f"(hi) : "l"(v));
}
__device__ __forceinline__ float ex2(float x) {
    float r;
    asm("ex2.approx.f32 %0, %1;" : "=f"(r) : "f"(x));
    return r;
}

// ================= Kernel A: odd-pixel decimation + 3 fused 1x1 projections =================
__global__ void proj_kernel(const float* __restrict__ x,
                            const float* __restrict__ gw, const float* __restrict__ gb,
                            const float* __restrict__ tw, const float* __restrict__ tb,
                            const float* __restrict__ pw, const float* __restrict__ pb) {
    __shared__ float swg[IC * CC], swt[IC * CC], swp[IC * CC];
    __shared__ float sbg[IC], sbt[IC], sbp[IC];
    int tid = threadIdx.x;
    for (int i = tid; i < IC * CC; i += blockDim.x) { swg[i] = gw[i]; swt[i] = tw[i]; swp[i] = pw[i]; }
    if (tid < IC) { sbg[tid] = gb[tid]; sbt[tid] = tb[tid]; sbp[tid] = pb[tid]; }
    if (blockIdx.x == 0 && tid < CC) { d_csum[tid] = 0.f; d_csq[tid] = 0.f; }
    __syncthreads();

    int gidx = blockIdx.x * blockDim.x + tid;
    int b = gidx >> 12;
    int p = gidx & (NPIX - 1);
    int oh = p >> 6, ow = p & 63;
    const float* xb = x + ((size_t)(b * CC) * 128 + 2 * oh + 1) * 128 + 2 * ow + 1;

    float ag[IC], at[IC], ap[IC];
#pragma unroll
    for (int o = 0; o < IC; o++) { ag[o] = 0.f; at[o] = 0.f; ap[o] = 0.f; }

    for (int c = 0; c < CC; c++) {
        float xv = xb[(size_t)c * 128 * 128];
#pragma unroll
        for (int o = 0; o < IC; o++) {
            ag[o] += swg[o * CC + c] * xv;
            at[o] += swt[o * CC + c] * xv;
            ap[o] += swp[o * CC + c] * xv;
        }
    }
    const float L2E = 1.4426950408889634f;
    float* tho = d_th + (size_t)gidx * IC;
    float* pho = d_ph + (size_t)gidx * IC;
    float* gxo = d_gx + (size_t)gidx * IC;
#pragma unroll
    for (int o = 0; o < IC; o++) {
        tho[o] = (at[o] + sbt[o]) * L2E;
        pho[o] = ap[o] + sbp[o];
        gxo[o] = ag[o] + sbg[o];
    }
}

// ================= Kernel B: streaming softmax attention, 2 queries/thread =================
__global__ void __launch_bounds__(512, 1) attn_kernel() {
    __shared__ float sk[128 * IC];
    __shared__ float sg[128 * IC];
    int tid = threadIdx.x;
    int b  = blockIdx.z;
    int ks = blockIdx.y;
    int q0 = blockIdx.x * 1024 + tid;
    int q1 = q0 + 512;

    const unsigned long long* qpa = (const unsigned long long*)(d_th + ((size_t)b * NPIX + q0) * IC);
    const unsigned long long* qpb = (const unsigned long long*)(d_th + ((size_t)b * NPIX + q1) * IC);
    unsigned long long q2a[8], q2b[8];
#pragma unroll
    for (int i = 0; i < 8; i++) { q2a[i] = qpa[i]; q2b[i] = qpb[i]; }

    unsigned long long acca[8], accb[8];
#pragma unroll
    for (int i = 0; i < 8; i++) { acca[i] = 0ull; accb[i] = 0ull; }
    float la = 0.f, lb = 0.f;

    int k0 = ks * (NPIX / KSPLIT);
    for (int kt = 0; kt < NPIX / KSPLIT; kt += 128) {
        const float4* srck = (const float4*)(d_ph + ((size_t)b * NPIX + k0 + kt) * IC);
        const float4* srcg = (const float4*)(d_gx + ((size_t)b * NPIX + k0 + kt) * IC);
        ((float4*)sk)[tid] = srck[tid];
        ((float4*)sg)[tid] = srcg[tid];
        __syncthreads();

        const unsigned long long* k2 = (const unsigned long long*)sk;
        const unsigned long long* g2 = (const unsigned long long*)sg;
#pragma unroll 2
        for (int j = 0; j < 128; j++) {
            const unsigned long long* kj = k2 + j * 8;
            const unsigned long long* gj = g2 + j * 8;
            unsigned long long sa = f2mul(q2a[0], kj[0]);
            unsigned long long sb = f2mul(q2b[0], kj[0]);
#pragma unroll
            for (int i = 1; i < 8; i++) {
                sa = f2fma(q2a[i], kj[i], sa);
                sb = f2fma(q2b[i], kj[i], sb);
            }
            float alo, ahi, blo, bhi;
            f2unpack(sa, alo, ahi);
            f2unpack(sb, blo, bhi);
            float ea = ex2(alo + ahi);
            float eb = ex2(blo + bhi);
            la += ea; lb += eb;
            unsigned long long pa2 = f2pack(ea, ea);
            unsigned long long pb2 = f2pack(eb, eb);
#pragma unroll
            for (int i = 0; i < 8; i++) {
                acca[i] = f2fma(pa2, gj[i], acca[i]);
                accb[i] = f2fma(pb2, gj[i], accb[i]);
            }
        }
        __syncthreads();
    }

    unsigned long long* paa = (unsigned long long*)(d_pacc + (((size_t)ks * BB + b) * NPIX + q0) * IC);
    unsigned long long* pab = (unsigned long long*)(d_pacc + (((size_t)ks * BB + b) * NPIX + q1) * IC);
#pragma unroll
    for (int i = 0; i < 8; i++) { paa[i] = acca[i]; pab[i] = accb[i]; }
    d_pl[((size_t)ks * BB + b) * NPIX + q0] = la;
    d_pl[((size_t)ks * BB + b) * NPIX + q1] = lb;
}

// ================= Kernel B2: combine partials + out-projection (+bias) at low res =========
__global__ void combine_proj_kernel(const float* __restrict__ ow_, const float* __restrict__ ob_) {
    __shared__ float sy[64 * IC];
    __shared__ float sw[CC * IC];
    __shared__ float sob[CC];
    int tid = threadIdx.x;
    int b = blockIdx.x >> 6;
    int nbase = (blockIdx.x & 63) * 64;

    for (int i = tid; i < CC * IC; i += 256) sw[i] = ow_[i];
    if (tid < CC) sob[tid] = ob_[tid];

    {
        int n = nbase + (tid >> 2);
        int f4 = tid & 3;
        float l = 0.f;
        float4 acc = make_float4(0.f, 0.f, 0.f, 0.f);
#pragma unroll
        for (int ks = 0; ks < KSPLIT; ks++) {
            size_t base = ((size_t)ks * BB + b) * NPIX + n;
            l += d_pl[base];
            float4 v = ((const float4*)(d_pacc + base * IC))[f4];
            acc.x += v.x; acc.y += v.y; acc.z += v.z; acc.w += v.w;
        }
        float inv = 1.f / l;
        float4* dst = (float4*)(sy + (tid >> 2) * IC) + f4;
        *dst = make_float4(acc.x * inv, acc.y * inv, acc.z * inv, acc.w * inv);
    }
    __syncthreads();

    {
        int p = tid & 63;
        int cbase = (tid >> 6) * 16;
        float4 yv0 = ((const float4*)(sy + p * IC))[0];
        float4 yv1 = ((const float4*)(sy + p * IC))[1];
        float4 yv2 = ((const float4*)(sy + p * IC))[2];
        float4 yv3 = ((const float4*)(sy + p * IC))[3];
        float* out = d_yp + ((size_t)b * CC + cbase) * NPIX + nbase + p;
#pragma unroll
        for (int cc = 0; cc < 16; cc++) {
            const float* wr = sw + (cbase + cc) * IC;
            float4 w0 = ((const float4*)wr)[0];
            float4 w1 = ((const float4*)wr)[1];
            float4 w2 = ((const float4*)wr)[2];
            float4 w3 = ((const float4*)wr)[3];
            float acc = sob[cbase + cc]
                      + w0.x * yv0.x + w0.y * yv0.y + w0.z * yv0.z + w0.w * yv0.w
                      + w1.x * yv1.x + w1.y * yv1.y + w1.z * yv1.z + w1.w * yv1.w
                      + w2.x * yv2.x + w2.y * yv2.y + w2.z * yv2.z + w2.w * yv2.w
                      + w3.x * yv3.x + w3.y * yv3.y + w3.z * yv3.z + w3.w * yv3.w;
            out[(size_t)cc * NPIX] = acc;
        }
    }
}

// ================= Kernel C: per-channel x2 upsample + residual + BN stats =================
__global__ void up_kernel(const float* __restrict__ x) {
    __shared__ float r1[256], r2[256];
    int tid = threadIdx.x;
    int bc  = blockIdx.x >> 4;
    int c   = bc & 63;
    int pix4 = (blockIdx.x & 15) * 256 + tid;
    int h  = pix4 >> 5;
    int m  = pix4 & 31;

    const float* yp = d_yp + (size_t)bc * NPIX;
    int j0, j1;
    if (h & 1) { j0 = j1 = h >> 1; }
    else       { j0 = max((h >> 1) - 1, 0); j1 = h >> 1; }
    const float* r0p = yp + j0 * 64;
    const float* r1p = yp + j1 * 64;

    int i0 = max(2 * m - 1, 0);
    float rm0 = 0.5f * (__ldg(r0p + i0)        + __ldg(r1p + i0));
    float rm1 = 0.5f * (__ldg(r0p + 2 * m)     + __ldg(r1p + 2 * m));
    float rm2 = 0.5f * (__ldg(r0p + 2 * m + 1) + __ldg(r1p + 2 * m + 1));

    size_t g4 = (size_t)bc * 4096 + pix4;
    float4 xv = ((const float4*)x)[g4];
    float4 z;
    z.x = xv.x + 0.5f * (rm0 + rm1);
    z.y = xv.y + rm1;
    z.z = xv.z + 0.5f * (rm1 + rm2);
    z.w = xv.w + rm2;
    ((float4*)d_z)[g4] = z;

    float s1 = z.x + z.y + z.z + z.w;
    float s2 = z.x * z.x + z.y * z.y + z.z * z.z + z.w * z.w;
    r1[tid] = s1; r2[tid] = s2;
    __syncthreads();
#pragma unroll
    for (int s = 128; s > 0; s >>= 1) {
        if (tid < s) { r1[tid] += r1[tid + s]; r2[tid] += r2[tid + s]; }
        __syncthreads();
    }
    if (tid == 0) {
        atomicAdd(&d_csum[c], r1[0]);
        atomicAdd(&d_csq[c],  r2[0]);
    }
}

// ================= Kernel D: batchnorm normalize =================
__global__ void bn_kernel(const float* __restrict__ gamma, const float* __restrict__ beta,
                          float* __restrict__ out) {
    int idx = blockIdx.x * blockDim.x + threadIdx.x;
    int c = (idx >> 12) & 63;
    const float inv = 1.f / 65536.f;
    float mean = d_csum[c] * inv;
    float var = d_csq[c] * inv - mean * mean;
    float rstd = rsqrtf(var + 1e-5f);
    float g = gamma[c] * rstd;
    float bt = beta[c] - mean * g;
    float4 z = ((const float4*)d_z)[idx];
    float4 o;
    o.x = z.x * g + bt; o.y = z.y * g + bt; o.z = z.z * g + bt; o.w = z.w * g + bt;
    ((float4*)out)[idx] = o;
}

// ================= launch =================
extern "C" void kernel_launch(void* const* d_in, const int* in_sizes, int n_in,
                              void* d_out, int out_size) {
    const float* x     = (const float*)d_in[0];
    const float* g_w   = (const float*)d_in[1];
    const float* g_b   = (const float*)d_in[2];
    const float* th_w  = (const float*)d_in[3];
    const float* th_b  = (const float*)d_in[4];
    const float* ph_w  = (const float*)d_in[5];
    const float* ph_b  = (const float*)d_in[6];
    const float* out_w = (const float*)d_in[7];
    const float* out_b = (const float*)d_in[8];
    const float* bn_g  = (const float*)d_in[9];
    const float* bn_b  = (const float*)d_in[10];
    float* out = (float*)d_out;

    proj_kernel<<<128, 128>>>(x, g_w, g_b, th_w, th_b, ph_w, ph_b);
    attn_kernel<<<dim3(4, KSPLIT, BB), 512>>>();
    combine_proj_kernel<<<256, 256>>>(out_w, out_b);
    up_kernel<<<4096, 256>>>(x);
    bn_kernel<<<4096, 256>>>(bn_g, bn_b, out);
}

// round 10
// speedup vs baseline: 1.1885x; 1.0168x over previous
#include <cuda_runtime.h>
#include <cstdint>

#define CC   64
#define IC   16
#define NPIX 4096   // 64x64
#define BB   4
#define KSPLIT 8

// ---------------- scratch (device globals; no allocation allowed) ----------------
__device__ float d_th [BB * NPIX * IC];              // queries (pre-scaled by log2e)
__device__ float d_kg [BB * NPIX * 32];              // interleaved: per key 16 K floats + 16 G floats
__device__ float d_pacc[KSPLIT * BB * NPIX * IC];    // split-K partial numerators
__device__ float d_pl  [KSPLIT * BB * NPIX];         // split-K partial denominators
__device__ float d_yp [BB * CC * NPIX];              // attention out, PROJECTED to 64ch, [b][c][n]
__device__ float d_z  [BB * CC * 128 * 128];         // residual sum pre-BN
__device__ float d_csum[CC];
__device__ float d_csq [CC];

// ---------------- f32x2 packed helpers ----------------
__device__ __forceinline__ unsigned long long f2fma(unsigned long long a, unsigned long long b, unsigned long long c) {
    unsigned long long d;
    asm("fma.rn.f32x2 %0, %1, %2, %3;" : "=l"(d) : "l"(a), "l"(b), "l"(c));
    return d;
}
__device__ __forceinline__ unsigned long long f2mul(unsigned long long a, unsigned long long b) {
    unsigned long long d;
    asm("mul.rn.f32x2 %0, %1, %2;" : "=l"(d) : "l"(a), "l"(b));
    return d;
}
__device__ __forceinline__ unsigned long long f2pack(float lo, float hi) {
    unsigned long long d;
    asm("mov.b64 %0, {%1, %2};" : "=l"(d) : "f"(lo), "f"(hi));
    return d;
}
__device__ __forceinline__ void f2unpack(unsigned long long v, float& lo, float& hi) {
    asm("mov.b64 {%0, %1}, %2;" : "=f"(lo), "=f"(hi) : "l"(v));
}
__device__ __forceinline__ float ex2(float x) {
    float r;
    asm("ex2.approx.f32 %0, %1;" : "=f"(r) : "f"(x));
    return r;
}

// ================= Kernel A: odd-pixel decimation + 3 fused 1x1 projections =================
// xd[oh,ow] = x[2oh+1, 2ow+1]; theta pre-scaled by log2e; K and G written interleaved.
__global__ void proj_kernel(const float* __restrict__ x,
                            const float* __restrict__ gw, const float* __restrict__ gb,
                            const float* __restrict__ tw, const float* __restrict__ tb,
                            const float* __restrict__ pw, const float* __restrict__ pb) {
    __shared__ float swg[IC * CC], swt[IC * CC], swp[IC * CC];
    __shared__ float sbg[IC], sbt[IC], sbp[IC];
    int tid = threadIdx.x;
    for (int i = tid; i < IC * CC; i += blockDim.x) { swg[i] = gw[i]; swt[i] = tw[i]; swp[i] = pw[i]; }
    if (tid < IC) { sbg[tid] = gb[tid]; sbt[tid] = tb[tid]; sbp[tid] = pb[tid]; }
    if (blockIdx.x == 0 && tid < CC) { d_csum[tid] = 0.f; d_csq[tid] = 0.f; }  // re-zero stats each replay
    __syncthreads();

    int gidx = blockIdx.x * blockDim.x + tid;     // 0..16383 = b*4096 + p
    int b = gidx >> 12;
    int p = gidx & (NPIX - 1);
    int oh = p >> 6, ow = p & 63;
    const float* xb = x + ((size_t)(b * CC) * 128 + 2 * oh + 1) * 128 + 2 * ow + 1;

    float ag[IC], at[IC], ap[IC];
#pragma unroll
    for (int o = 0; o < IC; o++) { ag[o] = 0.f; at[o] = 0.f; ap[o] = 0.f; }

    for (int c = 0; c < CC; c++) {
        float xv = xb[(size_t)c * 128 * 128];
#pragma unroll
        for (int o = 0; o < IC; o++) {
            ag[o] += swg[o * CC + c] * xv;
            at[o] += swt[o * CC + c] * xv;
            ap[o] += swp[o * CC + c] * xv;
        }
    }
    const float L2E = 1.4426950408889634f;
    float* tho = d_th + (size_t)gidx * IC;
    float* kgo = d_kg + (size_t)gidx * 32;
#pragma unroll
    for (int o = 0; o < IC; o++) {
        tho[o]      = (at[o] + sbt[o]) * L2E;
        kgo[o]      =  ap[o] + sbp[o];          // K
        kgo[16 + o] =  ag[o] + sbg[o];          // G
    }
}

// ================= Kernel B: streaming softmax attention, 2 queries/thread ==============
// grid (4 qtiles, 8 ksplits, 4 batches) = 128 CTAs, 512 threads.
// Interleaved K/G tile: per key 8x LDS.128 instead of 16x LDS.64.
__global__ void __launch_bounds__(512, 1) attn_kernel() {
    __shared__ float skg[128 * 32];      // 16KB
    int tid = threadIdx.x;
    int b  = blockIdx.z;
    int ks = blockIdx.y;
    int q0 = blockIdx.x * 1024 + tid;
    int q1 = q0 + 512;

    const ulonglong2* qpa = (const ulonglong2*)(d_th + ((size_t)b * NPIX + q0) * IC);
    const ulonglong2* qpb = (const ulonglong2*)(d_th + ((size_t)b * NPIX + q1) * IC);
    unsigned long long q2a[8], q2b[8];
#pragma unroll
    for (int i = 0; i < 4; i++) {
        ulonglong2 va = qpa[i], vb = qpb[i];
        q2a[2 * i] = va.x; q2a[2 * i + 1] = va.y;
        q2b[2 * i] = vb.x; q2b[2 * i + 1] = vb.y;
    }

    unsigned long long acca[8], accb[8];
#pragma unroll
    for (int i = 0; i < 8; i++) { acca[i] = 0ull; accb[i] = 0ull; }
    float la = 0.f, lb = 0.f;

    int k0 = ks * (NPIX / KSPLIT);                 // 512 keys per CTA
    for (int kt = 0; kt < NPIX / KSPLIT; kt += 128) {
        const float4* src = (const float4*)(d_kg + ((size_t)b * NPIX + k0 + kt) * 32);
        ((float4*)skg)[tid]       = src[tid];
        ((float4*)skg)[tid + 512] = src[tid + 512];
        __syncthreads();

#pragma unroll 2
        for (int j = 0; j < 128; j++) {
            const ulonglong2* kg2 = (const ulonglong2*)(skg + j * 32);
            ulonglong2 kv0 = kg2[0], kv1 = kg2[1], kv2 = kg2[2], kv3 = kg2[3];
            unsigned long long sa = f2mul(q2a[0], kv0.x);
            unsigned long long sb = f2mul(q2b[0], kv0.x);
            sa = f2fma(q2a[1], kv0.y, sa);  sb = f2fma(q2b[1], kv0.y, sb);
            sa = f2fma(q2a[2], kv1.x, sa);  sb = f2fma(q2b[2], kv1.x, sb);
            sa = f2fma(q2a[3], kv1.y, sa);  sb = f2fma(q2b[3], kv1.y, sb);
            sa = f2fma(q2a[4], kv2.x, sa);  sb = f2fma(q2b[4], kv2.x, sb);
            sa = f2fma(q2a[5], kv2.y, sa);  sb = f2fma(q2b[5], kv2.y, sb);
            sa = f2fma(q2a[6], kv3.x, sa);  sb = f2fma(q2b[6], kv3.x, sb);
            sa = f2fma(q2a[7], kv3.y, sa);  sb = f2fma(q2b[7], kv3.y, sb);
            float alo, ahi, blo, bhi;
            f2unpack(sa, alo, ahi);
            f2unpack(sb, blo, bhi);
            float ea = ex2(alo + ahi);     // q pre-scaled by log2e
            float eb = ex2(blo + bhi);
            la += ea; lb += eb;
            unsigned long long pa2 = f2pack(ea, ea);
            unsigned long long pb2 = f2pack(eb, eb);
            ulonglong2 gv0 = kg2[4], gv1 = kg2[5], gv2 = kg2[6], gv3 = kg2[7];
            acca[0] = f2fma(pa2, gv0.x, acca[0]);  accb[0] = f2fma(pb2, gv0.x, accb[0]);
            acca[1] = f2fma(pa2, gv0.y, acca[1]);  accb[1] = f2fma(pb2, gv0.y, accb[1]);
            acca[2] = f2fma(pa2, gv1.x, acca[2]);  accb[2] = f2fma(pb2, gv1.x, accb[2]);
            acca[3] = f2fma(pa2, gv1.y, acca[3]);  accb[3] = f2fma(pb2, gv1.y, accb[3]);
            acca[4] = f2fma(pa2, gv2.x, acca[4]);  accb[4] = f2fma(pb2, gv2.x, accb[4]);
            acca[5] = f2fma(pa2, gv2.y, acca[5]);  accb[5] = f2fma(pb2, gv2.y, accb[5]);
            acca[6] = f2fma(pa2, gv3.x, acca[6]);  accb[6] = f2fma(pb2, gv3.x, accb[6]);
            acca[7] = f2fma(pa2, gv3.y, acca[7]);  accb[7] = f2fma(pb2, gv3.y, accb[7]);
        }
        __syncthreads();
    }

    unsigned long long* paa = (unsigned long long*)(d_pacc + (((size_t)ks * BB + b) * NPIX + q0) * IC);
    unsigned long long* pab = (unsigned long long*)(d_pacc + (((size_t)ks * BB + b) * NPIX + q1) * IC);
#pragma unroll
    for (int i = 0; i < 8; i++) { paa[i] = acca[i]; pab[i] = accb[i]; }
    d_pl[((size_t)ks * BB + b) * NPIX + q0] = la;
    d_pl[((size_t)ks * BB + b) * NPIX + q1] = lb;
}

// ================= Kernel B2: combine partials + out-projection (+bias) at low res =========
__global__ void combine_proj_kernel(const float* __restrict__ ow_, const float* __restrict__ ob_) {
    __shared__ float sy[64 * IC];
    __shared__ float sw[CC * IC];
    __shared__ float sob[CC];
    int tid = threadIdx.x;
    int b = blockIdx.x >> 6;
    int nbase = (blockIdx.x & 63) * 64;

    for (int i = tid; i < CC * IC; i += 256) sw[i] = ow_[i];
    if (tid < CC) sob[tid] = ob_[tid];

    {
        int n = nbase + (tid >> 2);
        int f4 = tid & 3;
        float l = 0.f;
        float4 acc = make_float4(0.f, 0.f, 0.f, 0.f);
#pragma unroll
        for (int ks = 0; ks < KSPLIT; ks++) {
            size_t base = ((size_t)ks * BB + b) * NPIX + n;
            l += d_pl[base];
            float4 v = ((const float4*)(d_pacc + base * IC))[f4];
            acc.x += v.x; acc.y += v.y; acc.z += v.z; acc.w += v.w;
        }
        float inv = 1.f / l;
        float4* dst = (float4*)(sy + (tid >> 2) * IC) + f4;
        *dst = make_float4(acc.x * inv, acc.y * inv, acc.z * inv, acc.w * inv);
    }
    __syncthreads();

    {
        int p = tid & 63;
        int cbase = (tid >> 6) * 16;
        float4 yv0 = ((const float4*)(sy + p * IC))[0];
        float4 yv1 = ((const float4*)(sy + p * IC))[1];
        float4 yv2 = ((const float4*)(sy + p * IC))[2];
        float4 yv3 = ((const float4*)(sy + p * IC))[3];
        float* out = d_yp + ((size_t)b * CC + cbase) * NPIX + nbase + p;
#pragma unroll
        for (int cc = 0; cc < 16; cc++) {
            const float* wr = sw + (cbase + cc) * IC;
            float4 w0 = ((const float4*)wr)[0];
            float4 w1 = ((const float4*)wr)[1];
            float4 w2 = ((const float4*)wr)[2];
            float4 w3 = ((const float4*)wr)[3];
            float acc = sob[cbase + cc]
                      + w0.x * yv0.x + w0.y * yv0.y + w0.z * yv0.z + w0.w * yv0.w
                      + w1.x * yv1.x + w1.y * yv1.y + w1.z * yv1.z + w1.w * yv1.w
                      + w2.x * yv2.x + w2.y * yv2.y + w2.z * yv2.z + w2.w * yv2.w
                      + w3.x * yv3.x + w3.y * yv3.y + w3.z * yv3.z + w3.w * yv3.w;
            out[(size_t)cc * NPIX] = acc;
        }
    }
}

// ================= Kernel C: per-channel x2 upsample + residual + BN stats =================
// taps at 0.5h-0.5: odd coord = copy, even coord = 0.5*(left+right), edge clamp.
// grid 1024 blocks, 256 threads, 4 float4 per thread; warp-shuffle reduction + RED.
__global__ void up_kernel(const float* __restrict__ x) {
    int tid = threadIdx.x;
    int bc  = blockIdx.x >> 2;                    // (b,c) plane
    int c   = bc & 63;
    const float* yp = d_yp + (size_t)bc * NPIX;

    float s1 = 0.f, s2 = 0.f;
#pragma unroll
    for (int it = 0; it < 4; it++) {
        int pix4 = (blockIdx.x & 3) * 1024 + it * 256 + tid;   // float4 index within plane
        int h = pix4 >> 5;
        int m = pix4 & 31;

        int j0, j1;
        if (h & 1) { j0 = j1 = h >> 1; }
        else       { j0 = max((h >> 1) - 1, 0); j1 = h >> 1; }
        const float* r0p = yp + j0 * 64;
        const float* r1p = yp + j1 * 64;

        int i0 = max(2 * m - 1, 0);
        float rm0 = 0.5f * (__ldg(r0p + i0)        + __ldg(r1p + i0));
        float rm1 = 0.5f * (__ldg(r0p + 2 * m)     + __ldg(r1p + 2 * m));
        float rm2 = 0.5f * (__ldg(r0p + 2 * m + 1) + __ldg(r1p + 2 * m + 1));

        size_t g4 = (size_t)bc * 4096 + pix4;
        float4 xv = ((const float4*)x)[g4];
        float4 z;
        z.x = xv.x + 0.5f * (rm0 + rm1);
        z.y = xv.y + rm1;
        z.z = xv.z + 0.5f * (rm1 + rm2);
        z.w = xv.w + rm2;
        ((float4*)d_z)[g4] = z;

        s1 += z.x + z.y + z.z + z.w;
        s2 += z.x * z.x + z.y * z.y + z.z * z.z + z.w * z.w;
    }
#pragma unroll
    for (int off = 16; off > 0; off >>= 1) {
        s1 += __shfl_xor_sync(0xffffffffu, s1, off);
        s2 += __shfl_xor_sync(0xffffffffu, s2, off);
    }
    if ((tid & 31) == 0) {
        atomicAdd(&d_csum[c], s1);
        atomicAdd(&d_csq[c],  s2);
    }
}

// ================= Kernel D: batchnorm normalize =================
__global__ void bn_kernel(const float* __restrict__ gamma, const float* __restrict__ beta,
                          float* __restrict__ out) {
    int idx = blockIdx.x * blockDim.x + threadIdx.x;  // float4 index
    int c = (idx >> 12) & 63;                         // 4096 float4 per (b,c) plane
    const float inv = 1.f / 65536.f;
    float mean = d_csum[c] * inv;
    float var = d_csq[c] * inv - mean * mean;
    float rstd = rsqrtf(var + 1e-5f);
    float g = gamma[c] * rstd;
    float bt = beta[c] - mean * g;
    float4 z = ((const float4*)d_z)[idx];
    float4 o;
    o.x = z.x * g + bt; o.y = z.y * g + bt; o.z = z.z * g + bt; o.w = z.w * g + bt;
    ((float4*)out)[idx] = o;
}

// ================= launch =================
extern "C" void kernel_launch(void* const* d_in, const int* in_sizes, int n_in,
                              void* d_out, int out_size) {
    const float* x     = (const float*)d_in[0];
    const float* g_w   = (const float*)d_in[1];
    const float* g_b   = (const float*)d_in[2];
    const float* th_w  = (const float*)d_in[3];
    const float* th_b  = (const float*)d_in[4];
    const float* ph_w  = (const float*)d_in[5];
    const float* ph_b  = (const float*)d_in[6];
    const float* out_w = (const float*)d_in[7];
    const float* out_b = (const float*)d_in[8];
    const float* bn_g  = (const float*)d_in[9];
    const float* bn_b  = (const float*)d_in[10];
    float* out = (float*)d_out;

    proj_kernel<<<128, 128>>>(x, g_w, g_b, th_w, th_b, ph_w, ph_b);
    attn_kernel<<<dim3(4, KSPLIT, BB), 512>>>();
    combine_proj_kernel<<<256, 256>>>(out_w, out_b);
    up_kernel<<<1024, 256>>>(x);
    bn_kernel<<<4096, 256>>>(bn_g, bn_b, out);
}

// round 16
// speedup vs baseline: 3.3911x; 2.8532x over previous
#include <cuda_runtime.h>
#include <cuda_bf16.h>
#include <cstdint>

#define CC   64
#define IC   16
#define NPIX 4096   // 64x64
#define BB   4

// ---------------- scratch (device globals) ----------------
__device__ __nv_bfloat16 d_th_hl[BB * NPIX * 32];   // per q: 16 hi then 16 lo (theta * log2e)
__device__ __nv_bfloat16 d_ph_hl[BB * NPIX * 32];   // per key: 16 hi then 16 lo
__device__ __nv_bfloat16 d_gThi[BB * IC * NPIX];    // transposed values, hi  [b][ch][key]
__device__ __nv_bfloat16 d_gTlo[BB * IC * NPIX];    // transposed values, lo
__device__ float d_yp [BB * CC * NPIX];             // attention out projected to 64ch, [b][c][n]
__device__ float d_z  [BB * CC * 128 * 128];
__device__ float d_csum[CC];
__device__ float d_csq [CC];

// ---------------- helpers ----------------
__device__ __forceinline__ float ex2(float x) {
    float r; asm("ex2.approx.f32 %0, %1;" : "=f"(r) : "f"(x)); return r;
}
// pack two floats to bf16x2: first arg -> low half
__device__ __forceinline__ uint32_t packbf(float lo_elem, float hi_elem) {
    uint32_t r;
    asm("cvt.rn.bf16x2.f32 %0, %1, %2;" : "=r"(r) : "f"(hi_elem), "f"(lo_elem));
    return r;
}
__device__ __forceinline__ float lof(uint32_t w) { return __uint_as_float(w << 16); }
__device__ __forceinline__ float hif(uint32_t w) { return __uint_as_float(w & 0xFFFF0000u); }
__device__ __forceinline__ uint32_t smem_u32(const void* p) {
    uint32_t a;
    asm("{ .reg .u64 t; cvta.to.shared.u64 t, %1; cvt.u32.u64 %0, t; }" : "=r"(a) : "l"(p));
    return a;
}
// m16n8k16 bf16 MMA (sm_80 baseline PTX -> HMMA on sm_103a)
__device__ __forceinline__ void mma16816(float* c, const uint32_t* a, const uint32_t* b) {
    asm volatile("mma.sync.aligned.m16n8k16.row.col.f32.bf16.bf16.f32 "
        "{%0,%1,%2,%3}, {%4,%5,%6,%7}, {%8,%9}, {%0,%1,%2,%3};"
        : "+f"(c[0]), "+f"(c[1]), "+f"(c[2]), "+f"(c[3])
        : "r"(a[0]), "r"(a[1]), "r"(a[2]), "r"(a[3]), "r"(b[0]), "r"(b[1]));
}
#define CPA(dst, src) asm volatile("cp.async.cg.shared.global [%0], [%1], 16;" :: "r"(dst), "l"(src) : "memory")
#define CP_COMMIT()   asm volatile("cp.async.commit_group;" ::: "memory")
#define CP_WAIT(n)    asm volatile("cp.async.wait_group %0;" :: "n"(n) : "memory")

// ================= Kernel A: decimation + 3 projections + bf16 hi/lo splits =================
// grid 256 (= 4 b x 64 rows), 256 threads.
__global__ void __launch_bounds__(256) proj_kernel(const float* __restrict__ x,
        const float* __restrict__ gw, const float* __restrict__ gb,
        const float* __restrict__ tw, const float* __restrict__ tb,
        const float* __restrict__ pw, const float* __restrict__ pb) {
    __shared__ float swg[1024], swt[1024], swp[1024];
    __shared__ float sbias[48];
    __shared__ float sred[4096];
    int tid = threadIdx.x;
    for (int i = tid; i < 1024; i += 256) { swg[i] = gw[i]; swt[i] = tw[i]; swp[i] = pw[i]; }
    if (tid < 16) { sbias[tid] = gb[tid]; sbias[16 + tid] = tb[tid]; sbias[32 + tid] = pb[tid]; }
    if (blockIdx.x == 0 && tid < 64) { d_csum[tid] = 0.f; d_csq[tid] = 0.f; }
    __syncthreads();

    int b  = blockIdx.x >> 6;
    int pg = blockIdx.x & 63;       // output row oh
    int p  = tid & 63;              // output col ow
    int grp = tid >> 6;             // channel quarter

    const float* xb = x + ((size_t)(b * CC + grp * 16) * 128 + 2 * pg + 1) * 128 + 2 * p + 1;
    float ag[16], at[16], ap[16];
#pragma unroll
    for (int o = 0; o < 16; o++) { ag[o] = 0.f; at[o] = 0.f; ap[o] = 0.f; }
#pragma unroll
    for (int c16 = 0; c16 < 16; c16++) {
        float xv = xb[(size_t)c16 * 16384];
        int c = grp * 16 + c16;
#pragma unroll
        for (int o = 0; o < 16; o++) {
            ag[o] += swg[o * 64 + c] * xv;
            at[o] += swt[o * 64 + c] * xv;
            ap[o] += swp[o * 64 + c] * xv;
        }
    }
    const float L2E = 1.4426950408889634f;

    // ---- theta (scaled by log2e) ----
#pragma unroll
    for (int o = 0; o < 16; o++) sred[grp * 1024 + p * 16 + o] = at[o];
    __syncthreads();
    for (int r = tid; r < 1024; r += 256) {
        int pp = r >> 4, oo = r & 15;
        float v = sred[pp*16+oo] + sred[1024+pp*16+oo] + sred[2048+pp*16+oo] + sred[3072+pp*16+oo];
        v = (v + sbias[16 + oo]) * L2E;
        __nv_bfloat16 h = __float2bfloat16_rn(v);
        size_t gq = ((size_t)b * NPIX + pg * 64 + pp) * 32;
        d_th_hl[gq + oo]      = h;
        d_th_hl[gq + 16 + oo] = __float2bfloat16_rn(v - __bfloat162float(h));
    }
    __syncthreads();
    // ---- phi ----
#pragma unroll
    for (int o = 0; o < 16; o++) sred[grp * 1024 + p * 16 + o] = ap[o];
    __syncthreads();
    for (int r = tid; r < 1024; r += 256) {
        int pp = r >> 4, oo = r & 15;
        float v = sred[pp*16+oo] + sred[1024+pp*16+oo] + sred[2048+pp*16+oo] + sred[3072+pp*16+oo];
        v = v + sbias[32 + oo];
        __nv_bfloat16 h = __float2bfloat16_rn(v);
        size_t gq = ((size_t)b * NPIX + pg * 64 + pp) * 32;
        d_ph_hl[gq + oo]      = h;
        d_ph_hl[gq + 16 + oo] = __float2bfloat16_rn(v - __bfloat162float(h));
    }
    __syncthreads();
    // ---- g (transposed) ----
#pragma unroll
    for (int o = 0; o < 16; o++) sred[grp * 1024 + p * 16 + o] = ag[o];
    __syncthreads();
    for (int r = tid; r < 1024; r += 256) {
        int pp = r >> 4, oo = r & 15;
        float v = sred[pp*16+oo] + sred[1024+pp*16+oo] + sred[2048+pp*16+oo] + sred[3072+pp*16+oo];
        v = v + sbias[oo];
        __nv_bfloat16 h = __float2bfloat16_rn(v);
        size_t gi = ((size_t)b * IC + oo) * NPIX + pg * 64 + pp;
        d_gThi[gi] = h;
        d_gTlo[gi] = __float2bfloat16_rn(v - __bfloat162float(h));
    }
}

// ================= Kernel B: mma.sync flash attention + fused out-projection =================
// grid (64 qtiles of 64 rows, 4 batches) = 256 CTAs, 128 threads (4 warps, 16 q-rows/warp).
// Key tile = 128 keys, double-buffered via cp.async.
// Y gemm B operand: G^T rows = channels (0-15), row 16 = ones (denominator), 17-23 = zero.
__global__ void __launch_bounds__(128, 2) attn_mma_kernel(const float* __restrict__ ow_,
                                                          const float* __restrict__ ob_) {
    __shared__ uint32_t s_ph[2][2048];          // 128 keys x 32 bf16 (hi|lo)     8KB x2
    __shared__ uint32_t s_gh[2][24 * 68];       // 24 ch-rows x 136 bf16 (pad 8)  6528B x2
    __shared__ uint32_t s_gl[2][16 * 68];       // 16 ch-rows x 136 bf16          4352B x2
    __shared__ float    s_y[64][17];
    __shared__ float    s_w[1024];
    __shared__ float    s_ob[64];

    int tid  = threadIdx.x;
    int wid  = tid >> 5, lane = tid & 31;
    int g    = lane >> 2, tg = lane & 3;
    int b    = blockIdx.y;
    int q0   = blockIdx.x * 64;
    int warpQ = wid * 16;

    for (int i = tid; i < 1024; i += 128) s_w[i] = ow_[i];
    if (tid < 64) s_ob[tid] = ob_[tid];

    // G rows 16-23: ones row (16) for denominator, zeros elsewhere; both buffers, set once.
    for (int i = tid; i < 8 * 68; i += 128) {
        int row = 16 + i / 68, col = i % 68;
        uint32_t v = (row == 16 && col < 64) ? 0x3F803F80u : 0u;   // bf16x2 {1.0,1.0}
        s_gh[0][row * 68 + col] = v;
        s_gh[1][row * 68 + col] = v;
    }

    // theta A-fragments (hi, lo) straight from gmem — once per CTA
    const uint32_t* thp = (const uint32_t*)d_th_hl + (size_t)(b * NPIX + q0 + warpQ) * 16;
    uint32_t ahi[4], alo[4];
    ahi[0] = thp[g*16 + tg];       ahi[1] = thp[(g+8)*16 + tg];
    ahi[2] = thp[g*16 + tg + 4];   ahi[3] = thp[(g+8)*16 + tg + 4];
    alo[0] = thp[g*16 + tg + 8];   alo[1] = thp[(g+8)*16 + tg + 8];
    alo[2] = thp[g*16 + tg + 12];  alo[3] = thp[(g+8)*16 + tg + 12];

    uint32_t sphb[2] = { smem_u32(s_ph[0]), smem_u32(s_ph[1]) };
    uint32_t sghb[2] = { smem_u32(s_gh[0]), smem_u32(s_gh[1]) };
    uint32_t sglb[2] = { smem_u32(s_gl[0]), smem_u32(s_gl[1]) };

    auto load_tile = [&](int buf, int kt) {
        const char* psrc = (const char*)(d_ph_hl + (size_t)(b * NPIX + kt * 128) * 32);
#pragma unroll
        for (int i = 0; i < 4; i++) {
            int ch = tid + i * 128;
            CPA(sphb[buf] + ch * 16, psrc + ch * 16);
        }
#pragma unroll
        for (int i = 0; i < 2; i++) {
            int idx = tid + i * 128;
            int ch = idx >> 4, part = idx & 15;
            const char* sh = (const char*)(d_gThi + (size_t)(b * IC + ch) * NPIX + kt * 128);
            const char* sl = (const char*)(d_gTlo + (size_t)(b * IC + ch) * NPIX + kt * 128);
            CPA(sghb[buf] + ch * 272 + part * 16, sh + part * 16);
            CPA(sglb[buf] + ch * 272 + part * 16, sl + part * 16);
        }
    };

    float yc0[4] = {0,0,0,0}, yc1[4] = {0,0,0,0}, yc2[4] = {0,0,0,0};

    load_tile(0, 0);
    CP_COMMIT();

    for (int kt = 0; kt < 32; kt++) {
        int buf = kt & 1;
        if (kt < 31) { load_tile(buf ^ 1, kt + 1); CP_COMMIT(); CP_WAIT(1); }
        else CP_WAIT(0);
        __syncthreads();

        const uint32_t* ph = s_ph[buf];
        const uint32_t* gh = s_gh[buf];
        const uint32_t* gl = s_gl[buf];

#pragma unroll
        for (int s = 0; s < 8; s++) {
            // ---- S tiles j0 = 2s (keys s*16..+7), j1 = 2s+1 (keys s*16+8..+15) ----
            float c0[4] = {0,0,0,0}, c1[4] = {0,0,0,0};
            {
                int r0 = (s * 16 + g) * 16;
                uint32_t bh[2] = { ph[r0 + tg],     ph[r0 + tg + 4]  };
                uint32_t bl[2] = { ph[r0 + tg + 8], ph[r0 + tg + 12] };
                mma16816(c0, ahi, bh); mma16816(c0, alo, bh); mma16816(c0, ahi, bl);
                int r1 = (s * 16 + 8 + g) * 16;
                uint32_t bh1[2] = { ph[r1 + tg],     ph[r1 + tg + 4]  };
                uint32_t bl1[2] = { ph[r1 + tg + 8], ph[r1 + tg + 12] };
                mma16816(c1, ahi, bh1); mma16816(c1, alo, bh1); mma16816(c1, ahi, bl1);
            }
            // ---- softmax numerators; C-frag pair re-feeds as A-frag of k-step s ----
            float e0 = ex2(c0[0]), e1 = ex2(c0[1]), e2 = ex2(c0[2]), e3 = ex2(c0[3]);
            float f0 = ex2(c1[0]), f1 = ex2(c1[1]), f2 = ex2(c1[2]), f3 = ex2(c1[3]);
            uint32_t Phi[4], Plo[4];
            Phi[0] = packbf(e0, e1); Phi[1] = packbf(e2, e3);
            Phi[2] = packbf(f0, f1); Phi[3] = packbf(f2, f3);
            Plo[0] = packbf(e0 - lof(Phi[0]), e1 - hif(Phi[0]));
            Plo[1] = packbf(e2 - lof(Phi[1]), e3 - hif(Phi[1]));
            Plo[2] = packbf(f0 - lof(Phi[2]), f1 - hif(Phi[2]));
            Plo[3] = packbf(f2 - lof(Phi[3]), f3 - hif(Phi[3]));
            // ---- Y += P . G (k-step s over keys) ----
            int kb = s * 8 + tg;
            uint32_t g0h[2] = { gh[g * 68 + kb],        gh[g * 68 + kb + 4]        };
            uint32_t g1h[2] = { gh[(8 + g) * 68 + kb],  gh[(8 + g) * 68 + kb + 4]  };
            uint32_t g2h[2] = { gh[(16 + g) * 68 + kb], gh[(16 + g) * 68 + kb + 4] };
            uint32_t g0l[2] = { gl[g * 68 + kb],        gl[g * 68 + kb + 4]        };
            uint32_t g1l[2] = { gl[(8 + g) * 68 + kb],  gl[(8 + g) * 68 + kb + 4]  };
            mma16816(yc0, Phi, g0h); mma16816(yc1, Phi, g1h); mma16816(yc2, Phi, g2h);
            mma16816(yc0, Plo, g0h); mma16816(yc1, Plo, g1h); mma16816(yc2, Plo, g2h);
            mma16816(yc0, Phi, g0l); mma16816(yc1, Phi, g1l);
        }
        __syncthreads();
    }

    // denominator = Y column 16 (held by tg==0 lanes in yc2[0]/yc2[2])
    float d0 = __shfl_sync(0xffffffffu, yc2[0], lane & ~3);
    float d1 = __shfl_sync(0xffffffffu, yc2[2], lane & ~3);
    d0 = 1.f / d0; d1 = 1.f / d1;
    {
        int r0 = warpQ + g, r1 = warpQ + g + 8;
        s_y[r0][2*tg]     = yc0[0] * d0;  s_y[r0][2*tg + 1] = yc0[1] * d0;
        s_y[r1][2*tg]     = yc0[2] * d1;  s_y[r1][2*tg + 1] = yc0[3] * d1;
        s_y[r0][8 + 2*tg] = yc1[0] * d0;  s_y[r0][9 + 2*tg] = yc1[1] * d0;
        s_y[r1][8 + 2*tg] = yc1[2] * d1;  s_y[r1][9 + 2*tg] = yc1[3] * d1;
    }
    __syncthreads();

    // fused out-projection 16 -> 64 channels
    {
        int q  = tid & 63;
        int cb = (tid >> 6) * 32;
        float yv[16];
#pragma unroll
        for (int i = 0; i < 16; i++) yv[i] = s_y[q][i];
#pragma unroll 4
        for (int c = 0; c < 32; c++) {
            int cc = cb + c;
            const float* wr = s_w + cc * 16;
            float acc = s_ob[cc];
#pragma unroll
            for (int i = 0; i < 16; i++) acc += wr[i] * yv[i];
            d_yp[(size_t)(b * CC + cc) * NPIX + q0 + q] = acc;
        }
    }
}

// ================= Kernel C: per-channel x2 upsample + residual + BN stats =================
__global__ void up_kernel(const float* __restrict__ x) {
    int tid = threadIdx.x;
    int bc  = blockIdx.x >> 2;
    int c   = bc & 63;
    const float* yp = d_yp + (size_t)bc * NPIX;

    float s1 = 0.f, s2 = 0.f;
#pragma unroll
    for (int it = 0; it < 4; it++) {
        int pix4 = (blockIdx.x & 3) * 1024 + it * 256 + tid;
        int h = pix4 >> 5;
        int m = pix4 & 31;

        int j0, j1;
        if (h & 1) { j0 = j1 = h >> 1; }
        else       { j0 = max((h >> 1) - 1, 0); j1 = h >> 1; }
        const float* r0p = yp + j0 * 64;
        const float* r1p = yp + j1 * 64;

        int i0 = max(2 * m - 1, 0);
        float rm0 = 0.5f * (__ldg(r0p + i0)        + __ldg(r1p + i0));
        float rm1 = 0.5f * (__ldg(r0p + 2 * m)     + __ldg(r1p + 2 * m));
        float rm2 = 0.5f * (__ldg(r0p + 2 * m + 1) + __ldg(r1p + 2 * m + 1));

        size_t g4 = (size_t)bc * 4096 + pix4;
        float4 xv = ((const float4*)x)[g4];
        float4 z;
        z.x = xv.x + 0.5f * (rm0 + rm1);
        z.y = xv.y + rm1;
        z.z = xv.z + 0.5f * (rm1 + rm2);
        z.w = xv.w + rm2;
        ((float4*)d_z)[g4] = z;

        s1 += z.x + z.y + z.z + z.w;
        s2 += z.x * z.x + z.y * z.y + z.z * z.z + z.w * z.w;
    }
#pragma unroll
    for (int off = 16; off > 0; off >>= 1) {
        s1 += __shfl_xor_sync(0xffffffffu, s1, off);
        s2 += __shfl_xor_sync(0xffffffffu, s2, off);
    }
    if ((tid & 31) == 0) {
        atomicAdd(&d_csum[c], s1);
        atomicAdd(&d_csq[c],  s2);
    }
}

// ================= Kernel D: batchnorm normalize =================
__global__ void bn_kernel(const float* __restrict__ gamma, const float* __restrict__ beta,
                          float* __restrict__ out) {
    int idx = blockIdx.x * blockDim.x + threadIdx.x;
    int c = (idx >> 12) & 63;
    const float inv = 1.f / 65536.f;
    float mean = d_csum[c] * inv;
    float var = d_csq[c] * inv - mean * mean;
    float rstd = rsqrtf(var + 1e-5f);
    float g = gamma[c] * rstd;
    float bt = beta[c] - mean * g;
    float4 z = ((const float4*)d_z)[idx];
    float4 o;
    o.x = z.x * g + bt; o.y = z.y * g + bt; o.z = z.z * g + bt; o.w = z.w * g + bt;
    ((float4*)out)[idx] = o;
}

// ================= launch =================
extern "C" void kernel_launch(void* const* d_in, const int* in_sizes, int n_in,
                              void* d_out, int out_size) {
    const float* x     = (const float*)d_in[0];
    const float* g_w   = (const float*)d_in[1];
    const float* g_b   = (const float*)d_in[2];
    const float* th_w  = (const float*)d_in[3];
    const float* th_b  = (const float*)d_in[4];
    const float* ph_w  = (const float*)d_in[5];
    const float* ph_b  = (const float*)d_in[6];
    const float* out_w = (const float*)d_in[7];
    const float* out_b = (const float*)d_in[8];
    const float* bn_g  = (const float*)d_in[9];
    const float* bn_b  = (const float*)d_in[10];
    float* out = (float*)d_out;

    proj_kernel<<<256, 256>>>(x, g_w, g_b, th_w, th_b, ph_w, ph_b);
    attn_mma_kernel<<<dim3(64, BB), 128>>>(out_w, out_b);
    up_kernel<<<1024, 256>>>(x);
    bn_kernel<<<4096, 256>>>(bn_g, bn_b, out);
}